// round 16
// baseline (speedup 1.0000x reference)
#include <cuda_runtime.h>
#include <cuda_fp16.h>
#include <cstdint>
#include <cstddef>

// Problem dims
#define BATCH   128
#define NLAYERS 12
#define DFEAT   4096
#define DACT    768

// Tiling
#define CTA_N   128
#define NT      6                   // 768 / 128
#define KB      32
#define NCHUNK  78                  // sum_{i=0..11} (i+1)
#define NTASK   (NCHUNK * NT)       // 468 (c, tn) tasks
#define NFULL   296                 // tasks 0..295: full K (one occ-2 wave)
#define NSPLIT  (NTASK - NFULL)     // 172 tasks split into 4 quarter-K CTAs
#define NCTA    (NFULL + NSPLIT * 4)  // 984

// smem (halves). A: [128][ASTR], B: [32][BSTR].
// ASTR=40 halves (80B rows, 20-bank stride): ldmatrix rows hit 8 distinct banks.
// BSTR=136 halves (272B rows, 4-bank stride): ldmatrix rows distinct.
#define ASTR    40
#define BSTR    136
#define AS_H    (BATCH * ASTR)      // 5120 halves
#define BS_H    (KB * BSTR)         // 4352 halves
#define STAGE_H (AS_H + BS_H)       // 9472 halves = 18944 B
#define NSTAGE  4
#define SMEM_BYTES (NSTAGE * STAGE_H * 2)   // 75776

// One 128x128 fp32 tile per CTA slot: 984 * 64KB = 64.5 MB
#define TILE_ELEMS 16384
__device__ float g_scratch[(size_t)NCTA * TILE_ELEMS];
// x pre-converted to fp16, layout [l][b][k] (contiguous per l-slice): 12.6 MB
__device__ half g_x16[(size_t)NLAYERS * BATCH * DFEAT];

struct WPtrs { const float* w[NLAYERS]; };

__device__ __forceinline__ uint32_t smem_u32(const void* p) {
    uint32_t a;
    asm("{ .reg .u64 t; cvta.to.shared.u64 t, %1; cvt.u32.u64 %0, t; }" : "=r"(a) : "l"(p));
    return a;
}

__device__ __forceinline__ uint2 pack4(float4 v) {
    half2 h0 = __floats2half2_rn(v.x, v.y);   // .x in low half
    half2 h1 = __floats2half2_rn(v.z, v.w);
    uint2 r;
    r.x = *(uint32_t*)&h0;
    r.y = *(uint32_t*)&h1;
    return r;
}

__device__ __forceinline__ void cp_async16(uint32_t smem_dst, const void* gptr) {
    asm volatile("cp.async.cg.shared.global [%0], [%1], 16;"
                 :: "r"(smem_dst), "l"(gptr) : "memory");
}
__device__ __forceinline__ void cp_commit() {
    asm volatile("cp.async.commit_group;" ::: "memory");
}
template <int N>
__device__ __forceinline__ void cp_wait() {
    asm volatile("cp.async.wait_group %0;" :: "n"(N) : "memory");
}

__device__ __forceinline__ void ldmx4(uint32_t* r, uint32_t addr) {
    asm volatile("ldmatrix.sync.aligned.m8n8.x4.shared.b16 {%0,%1,%2,%3}, [%4];"
                 : "=r"(r[0]), "=r"(r[1]), "=r"(r[2]), "=r"(r[3]) : "r"(addr));
}
__device__ __forceinline__ void ldmx4t(uint32_t* r, uint32_t addr) {
    asm volatile("ldmatrix.sync.aligned.m8n8.x4.trans.shared.b16 {%0,%1,%2,%3}, [%4];"
                 : "=r"(r[0]), "=r"(r[1]), "=r"(r[2]), "=r"(r[3]) : "r"(addr));
}

__device__ __forceinline__ void mma_fp16(float* c, const uint32_t* a, const uint32_t* b) {
    asm volatile(
        "mma.sync.aligned.m16n8k16.row.col.f32.f16.f16.f32 "
        "{%0,%1,%2,%3}, {%4,%5,%6,%7}, {%8,%9}, {%0,%1,%2,%3};"
        : "+f"(c[0]), "+f"(c[1]), "+f"(c[2]), "+f"(c[3])
        : "r"(a[0]), "r"(a[1]), "r"(a[2]), "r"(a[3]), "r"(b[0]), "r"(b[1]));
}

// ---------------- x -> fp16 preconvert, [b][l][k] -> [l][b][k] ----------------
__global__ void xcvt_kernel(const float* __restrict__ x)
{
    int idx = blockIdx.x * blockDim.x + threadIdx.x;          // one per 8 elements
    const int nv = NLAYERS * BATCH * DFEAT / 8;
    if (idx >= nv) return;
    const int k8 = (idx % (DFEAT / 8)) * 8;
    const int r  = idx / (DFEAT / 8);
    const int b  = r % BATCH;
    const int l  = r / BATCH;
    const float* src = x + ((size_t)b * NLAYERS + l) * DFEAT + k8;
    float4 v0 = *(const float4*)src;
    float4 v1 = *(const float4*)(src + 4);
    uint2 p0 = pack4(v0), p1 = pack4(v1);
    uint4 o = make_uint4(p0.x, p0.y, p1.x, p1.y);
    *(uint4*)(g_x16 + ((size_t)l * BATCH + b) * DFEAT + k8) = o;
}

// ---------------- main GEMM ----------------
// Task t=(c,tn): out-tile [128 batch x 128 act-cols] of chunk c. Full tasks do
// K=4096; split tasks run as 4 CTAs of K=1024 each writing separate slots.
// 256 threads, 8 warps (2x4), warp tile 64x32, fp16 mma m16n8k16, fp32 accum.
// A via cp.async (distance 3, 4-stage ring, issued AFTER the stage barrier so
// a full __syncthreads separates compute(stage) from its overwrite);
// B via LDG->reg->STS (distance 2).
__global__ void __launch_bounds__(256, 2)
tri_gemm_kernel(WPtrs wp)
{
    extern __shared__ half smemh[];
    const uint32_t sb = smem_u32(smemh);
    const int tid  = threadIdx.x;
    const int lane = tid & 31;
    const int wid  = tid >> 5;
    const int warp_m = wid & 1;       // 0/1 -> m offset 0/64
    const int warp_n = wid >> 1;      // 0..3 -> n offset 0/32/64/96

    const int bid = blockIdx.x;
    int t, kstart, nkit;
    if (bid < NFULL) { t = bid; kstart = 0; nkit = DFEAT / KB; }        // 128
    else {
        t = NFULL + ((bid - NFULL) >> 2);
        kstart = ((bid - NFULL) & 3) << 10;     // q * 1024
        nkit = 1024 / KB;                        // 32
    }
    const int c  = t / NT;
    const int tn = t % NT;
    int i = 0;
    while (c >= (i + 1) * (i + 2) / 2) i++;
    const int l = c - i * (i + 1) / 2;

    const float* __restrict__ Wb = wp.w[i] + (size_t)l * DFEAT * DACT + (size_t)tn * CTA_N;
    const half*  __restrict__ xl = g_x16 + (size_t)l * BATCH * DFEAT;

    float acc[4][4][4];
#pragma unroll
    for (int mt = 0; mt < 4; mt++)
#pragma unroll
        for (int nt = 0; nt < 4; nt++)
#pragma unroll
            for (int q = 0; q < 4; q++) acc[mt][nt][q] = 0.f;

    // Loader mapping (256 threads)
    // A (fp16 gmem -> cp.async): rows a_row, a_row+64; 8 halves (16B) at col a_c8
    const int a_row = tid >> 2;
    const int a_c8  = (tid & 3) << 3;
    // B (fp32 gmem): row b_k, 4 floats at col b_c + 32j, j=0..3
    const int b_k = tid >> 3;
    const int b_c = (tid & 7) << 2;

    const half*  pA0 = xl + (size_t)a_row * DFEAT + kstart + a_c8;
    const half*  pA1 = pA0 + (size_t)64 * DFEAT;
    const float* pB  = Wb + (size_t)(kstart + b_k) * DACT + b_c;

    // smem store bases
    const uint32_t sA0b = sb + (uint32_t)(a_row * ASTR + a_c8) * 2;       // byte addr
    const uint32_t sA1b = sb + (uint32_t)((a_row + 64) * ASTR + a_c8) * 2;
    const uint32_t sB   = (uint32_t)(AS_H + b_k * BSTR + b_c);            // half index

    // ldmatrix address components (byte offsets within a stage)
    const uint32_t a_lm_row = (uint32_t)(warp_m * 64 + (lane & 7) + ((lane >> 3) & 1) * 8);
    const uint32_t a_lm_c   = (uint32_t)((lane >> 4) << 3);
    const uint32_t a_lm_off = (a_lm_row * ASTR + a_lm_c) * 2;
    const uint32_t b_lm_k   = (uint32_t)((lane & 7) + ((lane >> 3) & 1) * 8);
    const uint32_t b_lm_off = (uint32_t)(AS_H * 2) +
                              (b_lm_k * BSTR + warp_n * 32 + ((lane >> 4) << 3)) * 2;

    float4 bR[4];

    // prologue:
    // A: cp.async stages 0,1,2 (one commit group per stage)
#pragma unroll
    for (int ps = 0; ps < 3; ps++) {
        if (ps < nkit) {
            const uint32_t stb = (uint32_t)(ps * STAGE_H * 2);
            cp_async16(sA0b + stb, pA0);
            cp_async16(sA1b + stb, pA1);
            pA0 += KB; pA1 += KB;
        }
        cp_commit();
    }
    // B: LDG stage0 -> STS stage0; LDG stage1 -> regs
#pragma unroll
    for (int j = 0; j < 4; j++) bR[j] = *(const float4*)(pB + 32 * j);
    pB += (size_t)KB * DACT;
#pragma unroll
    for (int j = 0; j < 4; j++) *(uint2*)(smemh + sB + 32 * j) = pack4(bR[j]);
#pragma unroll
    for (int j = 0; j < 4; j++) bR[j] = *(const float4*)(pB + 32 * j);
    pB += (size_t)KB * DACT;

    int buf_sts = 1, buf_cmp = 0, buf_cpa = 3;
#pragma unroll 1
    for (int s = 0; s < nkit; s++) {
        // STS B(s+1) from regs (stage (s+1)%4 was last computed at iter s-3;
        // two barriers have passed since -> safe)
        if (s + 1 < nkit) {
            half* st = smemh + buf_sts * STAGE_H;
#pragma unroll
            for (int j = 0; j < 4; j++) *(uint2*)(st + sB + 32 * j) = pack4(bR[j]);
            buf_sts++; if (buf_sts == NSTAGE) buf_sts = 0;
        }
        // LDG B(s+2) -> regs
        if (s + 2 < nkit) {
#pragma unroll
            for (int j = 0; j < 4; j++) bR[j] = *(const float4*)(pB + 32 * j);
            pB += (size_t)KB * DACT;
        }
        // A(s) must be complete: commits issued = 3 + s, stage-s commit = #(s+1)
        // -> allow 2 pending.
        cp_wait<2>();
        __syncthreads();

        // cp.async A(s+3) into stage (s+3)%4 == (s-1)%4. Compute(s-1) finished
        // before the barrier above, so the overwrite is race-free. Always
        // commit (possibly empty) to keep the group count exact.
        if (s + 3 < nkit) {
            const uint32_t stb = (uint32_t)(buf_cpa * STAGE_H * 2);
            cp_async16(sA0b + stb, pA0);
            cp_async16(sA1b + stb, pA1);
            pA0 += KB; pA1 += KB;
        }
        cp_commit();
        buf_cpa++; if (buf_cpa == NSTAGE) buf_cpa = 0;

        const uint32_t stage_b = sb + (uint32_t)(buf_cmp * STAGE_H * 2);
        buf_cmp++; if (buf_cmp == NSTAGE) buf_cmp = 0;

#pragma unroll
        for (int kk = 0; kk < 2; kk++) {
            uint32_t af[4][4];
#pragma unroll
            for (int mt = 0; mt < 4; mt++)
                ldmx4(af[mt], stage_b + a_lm_off +
                      (uint32_t)((mt * 16 * ASTR + kk * 16) * 2));
            uint32_t bf[4][2];
            {
                uint32_t r[4];
                const uint32_t bo = stage_b + b_lm_off + (uint32_t)(kk * 16 * BSTR * 2);
                ldmx4t(r, bo);
                bf[0][0] = r[0]; bf[0][1] = r[1]; bf[1][0] = r[2]; bf[1][1] = r[3];
                ldmx4t(r, bo + 16 * 2);
                bf[2][0] = r[0]; bf[2][1] = r[1]; bf[3][0] = r[2]; bf[3][1] = r[3];
            }
#pragma unroll
            for (int mt = 0; mt < 4; mt++)
#pragma unroll
                for (int nt = 0; nt < 4; nt++)
                    mma_fp16(acc[mt][nt], af[mt], bf[nt]);
        }
    }

    // Epilogue: write this CTA's 128x128 tile to its private slot (deterministic)
    {
        float* dstc = g_scratch + (size_t)bid * TILE_ELEMS;
        const int r0 = warp_m * 64 + (lane >> 2);
        const int c0 = warp_n * 32 + (lane & 3) * 2;
#pragma unroll
        for (int mt = 0; mt < 4; mt++) {
#pragma unroll
            for (int nt = 0; nt < 4; nt++) {
                float* d0 = dstc + (size_t)(r0 + mt * 16) * CTA_N + c0 + nt * 8;
                *(float2*)d0 = make_float2(acc[mt][nt][0], acc[mt][nt][1]);
                float* d1 = d0 + 8 * CTA_N;
                *(float2*)d1 = make_float2(acc[mt][nt][2], acc[mt][nt][3]);
            }
        }
    }
}

// ---------------- reduce: out[b,i,a] = sum over l<=i of task (i,l)'s slot(s) ----------------
__global__ void reduce_kernel(float* __restrict__ out)
{
    const int nvec = BATCH * NLAYERS * DACT / 4;
    int idx = blockIdx.x * blockDim.x + threadIdx.x;
    if (idx >= nvec) return;
    const int a4 = (idx % (DACT / 4)) << 2;
    const int r  = idx / (DACT / 4);
    const int i  = r % NLAYERS;
    const int b  = r / NLAYERS;
    const int tn = a4 >> 7;
    const int ai = a4 & 127;
    const int c0 = i * (i + 1) / 2;
    const size_t eoff = (size_t)b * CTA_N + ai;

    float4 s = make_float4(0.f, 0.f, 0.f, 0.f);
#pragma unroll
    for (int l = 0; l < NLAYERS; l++) {
        if (l <= i) {
            const int t = (c0 + l) * NT + tn;
            if (t < NFULL) {
                float4 v = *(const float4*)(g_scratch + (size_t)t * TILE_ELEMS + eoff);
                s.x += v.x; s.y += v.y; s.z += v.z; s.w += v.w;
            } else {
                const float* p = g_scratch +
                    ((size_t)NFULL + (size_t)(t - NFULL) * 4) * TILE_ELEMS + eoff;
                float4 v0 = *(const float4*)(p);
                float4 v1 = *(const float4*)(p + TILE_ELEMS);
                float4 v2 = *(const float4*)(p + 2 * TILE_ELEMS);
                float4 v3 = *(const float4*)(p + 3 * TILE_ELEMS);
                s.x += v0.x + v1.x + v2.x + v3.x;
                s.y += v0.y + v1.y + v2.y + v3.y;
                s.z += v0.z + v1.z + v2.z + v3.z;
                s.w += v0.w + v1.w + v2.w + v3.w;
            }
        }
    }
    *(float4*)(out + (size_t)idx * 4) = s;
}

// ---------------- launch ----------------
extern "C" void kernel_launch(void* const* d_in, const int* in_sizes, int n_in,
                              void* d_out, int out_size)
{
    const float* x = (const float*)d_in[0];
    WPtrs wp;
    for (int j = 0; j < NLAYERS; j++) wp.w[j] = (const float*)d_in[1 + j];

    int nx = NLAYERS * BATCH * DFEAT / 8;
    xcvt_kernel<<<(nx + 255) / 256, 256>>>(x);

    cudaFuncSetAttribute(tri_gemm_kernel, cudaFuncAttributeMaxDynamicSharedMemorySize, SMEM_BYTES);
    tri_gemm_kernel<<<NCTA, 256, SMEM_BYTES>>>(wp);

    int nvec = BATCH * NLAYERS * DACT / 4;
    reduce_kernel<<<(nvec + 255) / 256, 256>>>((float*)d_out);
}